// round 2
// baseline (speedup 1.0000x reference)
#include <cuda_runtime.h>
#include <cuda_bf16.h>
#include <math.h>

// ---------------------------------------------------------------------------
// DBS_lstm: 3-layer LSTM (T=512, H=1024, batch=1) + output projection.
//
// Pipeline per layer l:
//   xg = h_prev_seq @ W_ih_l^T + (b_ih_l + b_hh_l)        (sgemm_nt_kernel)
//   recurrence over t: gates = xg[t] + W_hh_l @ h          (lstm_layer_kernel,
//                                                           persistent, grid-sync)
// Final: dbs = hs2 @ W_out^T                               (sgemm_nt_kernel)
// ---------------------------------------------------------------------------

#define T_FRAMES 512
#define HID      1024
#define GATES    (4 * HID)          // 4096
#define IN_DIM   85
#define OUT_N    (6890 * 3)         // 20670
#define NCTA_LSTM 128
#define NTHR_LSTM 256

// --------------------------- scratch (device globals) ----------------------
__device__ float  g_xg[T_FRAMES * GATES];          // 8 MB: per-layer input gates
__device__ float  g_hsA[T_FRAMES * HID];           // 2 MB
__device__ float  g_hsB[T_FRAMES * HID];           // 2 MB
__device__ float4 g_h4[HID / 4];                   // current hidden state
__device__ unsigned g_bar_count = 0;
__device__ unsigned g_bar_gen   = 0;

// --------------------------- generic SGEMM (C = A @ B^T + bias) ------------
// A: [M,K] row-major, B: [N,K] row-major, C: [M,N] row-major.
// C[m,n] = sum_k A[m,k] * B[n,k] + (b0?b0[n]:0) + (b1?b1[n]:0)
#define BM 64
#define BN 64
#define BK 16

__global__ __launch_bounds__(256)
void sgemm_nt_kernel(const float* __restrict__ A,
                     const float* __restrict__ B,
                     const float* __restrict__ b0,
                     const float* __restrict__ b1,
                     float* __restrict__ C,
                     int M, int N, int K)
{
    __shared__ float As[BK][68];   // As[k][m], pitch 68 keeps float4 alignment
    __shared__ float Bs[BK][68];   // Bs[k][n]

    const int tid = threadIdx.x;           // 256 threads
    const int tx  = tid & 15;              // n micro index
    const int ty  = tid >> 4;              // m micro index
    const int lk  = tid & 15;              // loader: k within tile
    const int lr  = tid >> 4;              // loader: row base (0..15)

    const int m0 = blockIdx.y * BM;
    const int n0 = blockIdx.x * BN;

    float acc[4][4];
#pragma unroll
    for (int i = 0; i < 4; ++i)
#pragma unroll
        for (int j = 0; j < 4; ++j) acc[i][j] = 0.f;

    for (int k0 = 0; k0 < K; k0 += BK) {
        const int k = k0 + lk;
        const bool kok = (k < K);
#pragma unroll
        for (int i = 0; i < 4; ++i) {
            const int m = m0 + lr + 16 * i;
            const int n = n0 + lr + 16 * i;
            As[lk][lr + 16 * i] = (kok && m < M) ? __ldg(&A[(size_t)m * K + k]) : 0.f;
            Bs[lk][lr + 16 * i] = (kok && n < N) ? __ldg(&B[(size_t)n * K + k]) : 0.f;
        }
        __syncthreads();

#pragma unroll
        for (int kk = 0; kk < BK; ++kk) {
            const float4 a = *(const float4*)&As[kk][ty * 4];
            const float4 b = *(const float4*)&Bs[kk][tx * 4];
            acc[0][0] = fmaf(a.x, b.x, acc[0][0]);
            acc[0][1] = fmaf(a.x, b.y, acc[0][1]);
            acc[0][2] = fmaf(a.x, b.z, acc[0][2]);
            acc[0][3] = fmaf(a.x, b.w, acc[0][3]);
            acc[1][0] = fmaf(a.y, b.x, acc[1][0]);
            acc[1][1] = fmaf(a.y, b.y, acc[1][1]);
            acc[1][2] = fmaf(a.y, b.z, acc[1][2]);
            acc[1][3] = fmaf(a.y, b.w, acc[1][3]);
            acc[2][0] = fmaf(a.z, b.x, acc[2][0]);
            acc[2][1] = fmaf(a.z, b.y, acc[2][1]);
            acc[2][2] = fmaf(a.z, b.z, acc[2][2]);
            acc[2][3] = fmaf(a.z, b.w, acc[2][3]);
            acc[3][0] = fmaf(a.w, b.x, acc[3][0]);
            acc[3][1] = fmaf(a.w, b.y, acc[3][1]);
            acc[3][2] = fmaf(a.w, b.z, acc[3][2]);
            acc[3][3] = fmaf(a.w, b.w, acc[3][3]);
        }
        __syncthreads();
    }

#pragma unroll
    for (int i = 0; i < 4; ++i) {
        const int m = m0 + ty * 4 + i;
        if (m >= M) continue;
#pragma unroll
        for (int j = 0; j < 4; ++j) {
            const int n = n0 + tx * 4 + j;
            if (n >= N) continue;
            float v = acc[i][j];
            if (b0) v += __ldg(&b0[n]);
            if (b1) v += __ldg(&b1[n]);
            C[(size_t)m * N + n] = v;
        }
    }
}

// --------------------------- persistent LSTM recurrence --------------------
// grid = 128 CTAs (all co-resident, 1/SM), 256 threads.
// CTA `cta` owns hidden units [cta*8, cta*8+8) => 32 rows of W_hh
// (4 gates x 8 units). Each row's 1024-element dot product is split across
// 8 lanes (128 elems each, held entirely in registers as 32 float4 per
// thread). Hidden state is exchanged through L2 (__stcg/__ldcg) with a
// software grid barrier between timesteps.

__device__ __forceinline__ float sigmf(float x) { return 1.f / (1.f + expf(-x)); }

__global__ __launch_bounds__(NTHR_LSTM, 1)
void lstm_layer_kernel(const float* __restrict__ Whh,     // [4096, 1024]
                       const float* __restrict__ xg,      // [512, 4096] (incl. biases)
                       float* __restrict__ hs_out)        // [512, 1024]
{
    __shared__ float4 hs4[HID / 4];   // 4 KB: broadcast copy of h_{t-1}
    __shared__ float  s_s[32];        // per-row dot sums
    __shared__ float  c_s[8];         // cell state for this CTA's units

    const int tid   = threadIdx.x;
    const int cta   = blockIdx.x;                // 0..127
    const int base  = cta * 8;                   // first hidden unit owned
    const int lane  = tid & 31;
    const int warp  = tid >> 5;
    const int row   = warp * 4 + (lane >> 3);    // 0..31 local row
    const int lane8 = lane & 7;                  // position within the row group
    const int g     = row >> 3;                  // gate 0..3 (i,f,g,o)
    const int u     = row & 7;                   // unit within CTA

    // Stage this thread's 128 weight elements into registers.
    const float4* wsrc = (const float4*)(Whh + (size_t)(g * HID + base + u) * HID);
    float4 wr[32];
#pragma unroll
    for (int jj = 0; jj < 32; ++jj)
        wr[jj] = __ldg(&wsrc[lane8 + 8 * jj]);

    if (tid < 8) c_s[tid] = 0.f;
    hs4[tid] = make_float4(0.f, 0.f, 0.f, 0.f);   // h_{-1} = 0 (tid<256 covers 256 f4)

    unsigned gen0 = 0;
    if (tid == 0) gen0 = *(volatile unsigned*)&g_bar_gen;  // barrier epoch at entry
    __syncthreads();

    for (int t = 0; t < T_FRAMES; ++t) {
        // ---- dot: sum over this lane's 128 columns ----
        float sum = 0.f;
#pragma unroll
        for (int jj = 0; jj < 32; ++jj) {
            const float4 h = hs4[lane8 + 8 * jj];   // 4-way broadcast, conflict-free
            sum = fmaf(wr[jj].x, h.x, sum);
            sum = fmaf(wr[jj].y, h.y, sum);
            sum = fmaf(wr[jj].z, h.z, sum);
            sum = fmaf(wr[jj].w, h.w, sum);
        }
        // reduce across the 8 lanes of each row group (bits 0..2)
        sum += __shfl_xor_sync(0xffffffffu, sum, 1);
        sum += __shfl_xor_sync(0xffffffffu, sum, 2);
        sum += __shfl_xor_sync(0xffffffffu, sum, 4);
        if (lane8 == 0) s_s[row] = sum;
        __syncthreads();

        // ---- gates + state update (8 threads, one per hidden unit) ----
        if (tid < 8) {
            const float* xr = xg + (size_t)t * GATES + base + tid;
            const float ai = s_s[tid]      + __ldg(xr);
            const float af = s_s[8 + tid]  + __ldg(xr + HID);
            const float ag = s_s[16 + tid] + __ldg(xr + 2 * HID);
            const float ao = s_s[24 + tid] + __ldg(xr + 3 * HID);
            const float i_ = sigmf(ai);
            const float f_ = sigmf(af);
            const float g_ = tanhf(ag);
            const float o_ = sigmf(ao);
            const float c  = f_ * c_s[tid] + i_ * g_;
            c_s[tid] = c;
            const float h = o_ * tanhf(c);
            __stcg(((float*)g_h4) + base + tid, h);   // L2-visible for other SMs
            hs_out[(size_t)t * HID + base + tid] = h;
            __threadfence();                          // publish before arrive
        }
        __syncthreads();

        // ---- software grid barrier (monotonic generation counter) ----
        if (tid == 0) {
            __threadfence();
            const unsigned prev = atomicAdd(&g_bar_count, 1u);
            if (prev == gridDim.x - 1) {
                *(volatile unsigned*)&g_bar_count = 0u;
                __threadfence();
                atomicAdd(&g_bar_gen, 1u);
            } else {
                const unsigned target = gen0 + (unsigned)t + 1u;
                while ((int)(*(volatile unsigned*)&g_bar_gen - target) < 0) { }
            }
        }
        __syncthreads();

        // ---- fetch the fully-assembled h_t for the next step ----
        if (t < T_FRAMES - 1) {
            hs4[tid] = __ldcg(((const float4*)g_h4) + tid);  // bypass stale L1
        }
        __syncthreads();
    }
}

// --------------------------- launch -----------------------------------------
extern "C" void kernel_launch(void* const* d_in, const int* in_sizes, int n_in,
                              void* d_out, int out_size)
{
    (void)in_sizes; (void)n_in; (void)out_size;

    // Inputs (metadata order):
    // 0: pose_beta_seq [512,85]
    // 1+4l: W_ih_l, 2+4l: W_hh_l, 3+4l: b_ih_l, 4+4l: b_hh_l   (l = 0..2)
    // 13: W_out [20670,1024]
    const float* x      = (const float*)d_in[0];
    const float* W_ih[3] = {(const float*)d_in[1], (const float*)d_in[5], (const float*)d_in[9]};
    const float* W_hh[3] = {(const float*)d_in[2], (const float*)d_in[6], (const float*)d_in[10]};
    const float* b_ih[3] = {(const float*)d_in[3], (const float*)d_in[7], (const float*)d_in[11]};
    const float* b_hh[3] = {(const float*)d_in[4], (const float*)d_in[8], (const float*)d_in[12]};
    const float* W_out  = (const float*)d_in[13];
    float* out = (float*)d_out;

    float *xg, *hsA, *hsB;
    cudaGetSymbolAddress((void**)&xg,  g_xg);
    cudaGetSymbolAddress((void**)&hsA, g_hsA);
    cudaGetSymbolAddress((void**)&hsB, g_hsB);

    const dim3 blk(256);
    const dim3 grid_xg(GATES / BN, T_FRAMES / BM);                 // (64, 8)
    const dim3 grid_out((OUT_N + BN - 1) / BN, T_FRAMES / BM);     // (323, 8)

    // ---- layer 0 ----
    sgemm_nt_kernel<<<grid_xg, blk>>>(x, W_ih[0], b_ih[0], b_hh[0], xg,
                                      T_FRAMES, GATES, IN_DIM);
    lstm_layer_kernel<<<NCTA_LSTM, NTHR_LSTM>>>(W_hh[0], xg, hsA);

    // ---- layer 1 ----
    sgemm_nt_kernel<<<grid_xg, blk>>>(hsA, W_ih[1], b_ih[1], b_hh[1], xg,
                                      T_FRAMES, GATES, HID);
    lstm_layer_kernel<<<NCTA_LSTM, NTHR_LSTM>>>(W_hh[1], xg, hsB);

    // ---- layer 2 ----
    sgemm_nt_kernel<<<grid_xg, blk>>>(hsB, W_ih[2], b_ih[2], b_hh[2], xg,
                                      T_FRAMES, GATES, HID);
    lstm_layer_kernel<<<NCTA_LSTM, NTHR_LSTM>>>(W_hh[2], xg, hsA);

    // ---- output projection: dbs = hs2 @ W_out^T ----
    sgemm_nt_kernel<<<grid_out, blk>>>(hsA, W_out, nullptr, nullptr, out,
                                       T_FRAMES, OUT_N, HID);
}